// round 4
// baseline (speedup 1.0000x reference)
#include <cuda_runtime.h>
#include <cuda_fp16.h>
#include <math.h>
#include <stdint.h>

// Problem constants: B=64, N=1024, D=8, S=16 -> DS=128, K=1024
#define NN    1024
#define BB    64
#define DS    128
#define KDIM  1024
#define CHUNK 64                     // K per stage
#define NCH   (KDIM / CHUNK)         // 16

// smem geometry: padded-linear rows, 128B data + 16B pad = 144B stride
#define ROWB     144
#define A_BYTES  (128 * ROWB)        // 18432
#define B_BYTES  (256 * ROWB)        // 36864
#define STG_SZ   (A_BYTES + B_BYTES) // 55296
#define NSTAGE   4
#define C_STRIDE 260                 // epilogue fp32 row stride (4-float pad)
#define SMEM_REQ (NSTAGE * STG_SZ + 2048)   // 223232

__device__ __forceinline__ uint32_t smem_u32(const void* p) {
    uint32_t a;
    asm("{ .reg .u64 t; cvta.to.shared.u64 t, %1; cvt.u32.u64 %0, t; }" : "=r"(a) : "l"(p));
    return a;
}
__device__ __forceinline__ void cp16(uint32_t dst, const void* src) {
    asm volatile("cp.async.cg.shared.global [%0], [%1], 16;" :: "r"(dst), "l"(src) : "memory");
}
__device__ __forceinline__ void ldm_x4(uint32_t* r, uint32_t addr) {
    asm volatile("ldmatrix.sync.aligned.m8n8.x4.shared.b16 {%0,%1,%2,%3}, [%4];"
                 : "=r"(r[0]), "=r"(r[1]), "=r"(r[2]), "=r"(r[3]) : "r"(addr));
}
__device__ __forceinline__ void mma16816(float* c, const uint32_t* a, uint32_t b0, uint32_t b1) {
    asm volatile("mma.sync.aligned.m16n8k16.row.col.f32.f16.f16.f32 "
                 "{%0,%1,%2,%3}, {%4,%5,%6,%7}, {%8,%9}, {%0,%1,%2,%3};"
                 : "+f"(c[0]), "+f"(c[1]), "+f"(c[2]), "+f"(c[3])
                 : "r"(a[0]), "r"(a[1]), "r"(a[2]), "r"(a[3]), "r"(b0), "r"(b1));
}

// ---------------- device scratch ------------------------------------------
__device__ __half g_A[NN * KDIM];        // M fp16, [o, i]            (2 MB)
__device__ __half g_X[BB * DS * KDIM];   // xT fp16, [(b*128+ds), i] (16 MB)

// ---------------- prep 1: M fp32 -> fp16, 16B per thread -------------------
__global__ void conv_M(const float* __restrict__ M) {
    const int i = blockIdx.x * 256 + threadIdx.x;        // 131072 threads
    const float4 v0 = ((const float4*)M)[2 * i];
    const float4 v1 = ((const float4*)M)[2 * i + 1];
    __half2 h[4];
    h[0] = __floats2half2_rn(v0.x, v0.y);
    h[1] = __floats2half2_rn(v0.z, v0.w);
    h[2] = __floats2half2_rn(v1.x, v1.y);
    h[3] = __floats2half2_rn(v1.z, v1.w);
    ((uint4*)g_A)[i] = *(uint4*)h;
}

// ---------------- prep 2: transpose x[b,i,ds] -> g_X[(b*128+ds), i] fp16 ---
// 64(i) x 32(ds) tiles; fp16 writes are 128B segments (32 half2 per row).
__global__ void transpose_x(const float* __restrict__ x) {
    __shared__ float t[64 * 33];
    const int b  = blockIdx.z;
    const int i0 = blockIdx.x * 64;
    const int d0 = blockIdx.y * 32;
    const int tid = threadIdx.x;

    const float* src = x + (size_t)b * (NN * DS) + (size_t)i0 * DS + d0;
#pragma unroll
    for (int idx = tid; idx < 64 * 32; idx += 256) {
        const int r = idx >> 5, c = idx & 31;
        t[r * 33 + c] = src[(size_t)r * DS + c];
    }
    __syncthreads();

    __half2* dst = (__half2*)g_X + (size_t)(b * DS + d0) * (KDIM / 2) + (i0 >> 1);
#pragma unroll
    for (int idx = tid; idx < 32 * 32; idx += 256) {
        const int dsr = idx >> 5, hc = idx & 31;
        dst[(size_t)dsr * (KDIM / 2) + hc] =
            __floats2half2_rn(t[(2 * hc) * 33 + dsr], t[(2 * hc + 1) * 33 + dsr]);
    }
}

// ---------------- GEMM (128o x 256n, n = 2 batches) + fused epilogue -------
// Grid (8, 32). Block 512 = 16 warps, warp tile m64 x n32 (2 m x 8 n).
// 4-stage cp.async pipeline; padded-linear smem (144B row stride).
__global__ void __launch_bounds__(512) gemm_neuron(
    const float* __restrict__ w_syn,    // [N, 128]
    const float* __restrict__ b_dend,   // [N, 8]
    const float* __restrict__ w_dend,   // [N, 8]
    const float* __restrict__ b_soma,   // [N]
    float* __restrict__ out)            // [B, N]
{
    extern __shared__ char smem[];
    const uint32_t sb = smem_u32(smem);
    const int tid  = threadIdx.x;
    const int wid  = tid >> 5, lane = tid & 31;
    const int wm   = wid & 1;           // m-warp: 64 rows
    const int wn   = wid >> 1;          // n-warp: 32 cols (0..7)
    const int o0   = blockIdx.x * 128;
    const int b0   = blockIdx.y * 2;

    // ldmatrix lane bases (linear + pad layout)
    uint32_t rowA[4], rowB[2];
#pragma unroll
    for (int mt = 0; mt < 4; mt++)
        rowA[mt] = (uint32_t)(wm * 64 + mt * 16 + (lane & 15)) * ROWB + (lane >> 4) * 16;
#pragma unroll
    for (int bt = 0; bt < 2; bt++)
        rowB[bt] = A_BYTES +
            (uint32_t)(wn * 32 + bt * 16 + ((lane >> 4) & 1) * 8 + (lane & 7)) * ROWB +
            ((lane >> 3) & 1) * 16;

    float acc[4][4][4];
#pragma unroll
    for (int mt = 0; mt < 4; mt++)
#pragma unroll
        for (int nt = 0; nt < 4; nt++)
#pragma unroll
            for (int q = 0; q < 4; q++) acc[mt][nt][q] = 0.f;

    const __half* gA = g_A + (size_t)o0 * KDIM;
    const __half* gB = g_X + (size_t)(b0 * DS) * KDIM;

#define STAGE(c) do {                                                           \
    const uint32_t _base = sb + ((c) & 3) * STG_SZ;                             \
    _Pragma("unroll")                                                           \
    for (int it = 0; it < 2; it++) {                                            \
        const int g = tid + it * 512;                                           \
        const int row = g >> 3, col = g & 7;                                    \
        cp16(_base + row * ROWB + col * 16,                                     \
             gA + (size_t)row * KDIM + (c) * CHUNK + col * 8);                  \
    }                                                                           \
    _Pragma("unroll")                                                           \
    for (int it = 0; it < 4; it++) {                                            \
        const int g = tid + it * 512;                                           \
        const int row = g >> 3, col = g & 7;                                    \
        cp16(_base + A_BYTES + row * ROWB + col * 16,                           \
             gB + (size_t)row * KDIM + (c) * CHUNK + col * 8);                  \
    }                                                                           \
    asm volatile("cp.async.commit_group;" ::: "memory");                        \
} while (0)

    STAGE(0); STAGE(1); STAGE(2);

    for (int c = 0; c < NCH; c++) {
        asm volatile("cp.async.wait_group 2;" ::: "memory");
        __syncthreads();
        if (c + 3 < NCH) STAGE(c + 3);   // overwrites buffer of chunk c-1 (done)

        const uint32_t base = sb + (c & 3) * STG_SZ;
#pragma unroll
        for (int kb = 0; kb < 4; kb++) {
            uint32_t a[4][4], bf[2][4];
#pragma unroll
            for (int mt = 0; mt < 4; mt++) ldm_x4(a[mt], base + rowA[mt] + kb * 32);
#pragma unroll
            for (int bt = 0; bt < 2; bt++) ldm_x4(bf[bt], base + rowB[bt] + kb * 32);
#pragma unroll
            for (int mt = 0; mt < 4; mt++)
#pragma unroll
                for (int nt = 0; nt < 4; nt++)
                    mma16816(acc[mt][nt], a[mt],
                             bf[nt >> 1][(nt & 1) * 2], bf[nt >> 1][(nt & 1) * 2 + 1]);
        }
    }
    __syncthreads();

    // ---- epilogue: frags -> C[128][C_STRIDE] fp32, then fused neuron math ----
    float* C = (float*)smem;
#pragma unroll
    for (int mt = 0; mt < 4; mt++)
#pragma unroll
        for (int nt = 0; nt < 4; nt++) {
            const int r  = wm * 64 + mt * 16 + (lane >> 2);
            const int cc = wn * 32 + nt * 8 + (lane & 3) * 2;
            C[r * C_STRIDE + cc]           = acc[mt][nt][0];
            C[r * C_STRIDE + cc + 1]       = acc[mt][nt][1];
            C[(r + 8) * C_STRIDE + cc]     = acc[mt][nt][2];
            C[(r + 8) * C_STRIDE + cc + 1] = acc[mt][nt][3];
        }
    __syncthreads();

    // thread = (row 0..127, quarter q 0..3): q -> (batch b_l = q>>1, half h = q&1)
    const int row = tid & 127;
    const int q   = tid >> 7;
    const int bl  = q >> 1, h = q & 1;
    const int o   = o0 + row;
    const int cb  = bl * 128 + h * 64;
    float td[4] = {0.f, 0.f, 0.f, 0.f};
    const float4* w4 = (const float4*)(w_syn + (size_t)o * 128 + h * 64);
#pragma unroll
    for (int j4 = 0; j4 < 16; j4++) {
        const float4 w = w4[j4];
        const float4 v = *(const float4*)&C[row * C_STRIDE + cb + j4 * 4];
        td[j4 >> 2] += v.x * w.x + v.y * w.y + v.z * w.z + v.w * w.w;
    }
    float sh = 0.f;
#pragma unroll
    for (int d = 0; d < 4; d++) {
        const int dd = h * 4 + d;
        sh += tanhf(td[d] + b_dend[o * 8 + dd]) * w_dend[o * 8 + dd];
    }
    float* spart = (float*)(smem + 128 * C_STRIDE * 4);
    spart[q * 128 + row] = sh;
    __syncthreads();
    if (tid < 256) {
        const int bs = tid >> 7, r2 = tid & 127;
        const float s = spart[(bs * 2) * 128 + r2] + spart[(bs * 2 + 1) * 128 + r2]
                      + b_soma[o0 + r2];
        out[(b0 + bs) * NN + o0 + r2] = 1.0f / (1.0f + expf(-s));
    }
}

// ---------------------------------------------------------------------------
extern "C" void kernel_launch(void* const* d_in, const int* in_sizes, int n_in,
                              void* d_out, int out_size)
{
    const float* x      = (const float*)d_in[0];   // [B, N, D, S]
    const float* M      = (const float*)d_in[1];   // [N, N]
    const float* w_syn  = (const float*)d_in[2];   // [N, D, S]
    const float* b_dend = (const float*)d_in[3];   // [N, D]
    const float* w_dend = (const float*)d_in[4];   // [N, D]
    const float* b_soma = (const float*)d_in[5];   // [N]
    float* out          = (float*)d_out;           // [B, N]

    cudaFuncSetAttribute(gemm_neuron, cudaFuncAttributeMaxDynamicSharedMemorySize, SMEM_REQ);

    conv_M<<<(NN * NN) / (256 * 8), 256>>>(M);
    transpose_x<<<dim3(NN / 64, DS / 32, BB), 256>>>(x);
    gemm_neuron<<<dim3(NN / 128, BB / 2), 512, SMEM_REQ>>>(w_syn, b_dend, w_dend, b_soma, out);
}